// round 10
// baseline (speedup 1.0000x reference)
#include <cuda_runtime.h>

// DyDepthwiseConvAtten: B=1024, N=100, C=256, K=3  (rows = 102400)
// Round 10: coalesced layout + 4 rows/warp. All 16 streaming LDG.128
// front-batched (8KB in flight/warp) so DRAM latency is fully covered even
// at low occupancy; invariants (Ww/gamma/beta/bw) amortized 4x. Each warp
// touches 16KB of contiguous q/v/out -> good HBM page locality.
// No smem, no barriers; butterflies batched for ILP.

#define C_DIM 256
#define LN_EPS 1e-5f
#define WARPS_PER_CTA 4
#define RPW 4

__global__ __launch_bounds__(WARPS_PER_CTA * 32)
void dydw_atten_kernel(const float* __restrict__ q,
                       const float* __restrict__ v,
                       const float* __restrict__ Ww,   // [3,256]
                       const float* __restrict__ bw,   // [3]
                       const float* __restrict__ gamma,
                       const float* __restrict__ beta,
                       float* __restrict__ out) {
    const int lane  = threadIdx.x & 31;
    const int wrp   = threadIdx.x >> 5;
    const int gwarp = blockIdx.x * WARPS_PER_CTA + wrp;

    const int c0 = 4 * lane;          // chunk 0: channels [c0, c0+4)
    const int c1 = 128 + 4 * lane;    // chunk 1: channels [c1, c1+4)

    size_t base[RPW];
    #pragma unroll
    for (int r = 0; r < RPW; r++)
        base[r] = (size_t)(gwarp * RPW + r) * C_DIM;

    // ---- front-batch ALL streaming loads: 16x LDG.128 ----
    float4 qv[RPW][2], vv4[RPW][2];
    #pragma unroll
    for (int r = 0; r < RPW; r++) {
        qv[r][0]  = __ldcs((const float4*)(q + base[r] + c0));
        qv[r][1]  = __ldcs((const float4*)(q + base[r] + c1));
        vv4[r][0] = __ldcs((const float4*)(v + base[r] + c0));
        vv4[r][1] = __ldcs((const float4*)(v + base[r] + c1));
    }

    // ---- invariants: once per warp, amortized over 4 rows ----
    const float4 w00 = *(const float4*)(Ww + c0);
    const float4 w01 = *(const float4*)(Ww + c1);
    const float4 w10 = *(const float4*)(Ww + C_DIM + c0);
    const float4 w11 = *(const float4*)(Ww + C_DIM + c1);
    const float4 w20 = *(const float4*)(Ww + 2*C_DIM + c0);
    const float4 w21 = *(const float4*)(Ww + 2*C_DIM + c1);
    const float bw0 = bw[0], bw1 = bw[1], bw2 = bw[2];

    // ---- dynamic-weight dots: 12 independent partials, batched butterfly ----
    float p[RPW][3];
    #pragma unroll
    for (int r = 0; r < RPW; r++) {
        const float4 a = qv[r][0], b = qv[r][1];
        p[r][0] = a.x*w00.x + a.y*w00.y + a.z*w00.z + a.w*w00.w
                + b.x*w01.x + b.y*w01.y + b.z*w01.z + b.w*w01.w;
        p[r][1] = a.x*w10.x + a.y*w10.y + a.z*w10.z + a.w*w10.w
                + b.x*w11.x + b.y*w11.y + b.z*w11.z + b.w*w11.w;
        p[r][2] = a.x*w20.x + a.y*w20.y + a.z*w20.z + a.w*w20.w
                + b.x*w21.x + b.y*w21.y + b.z*w21.z + b.w*w21.w;
    }
    #pragma unroll
    for (int off = 16; off > 0; off >>= 1) {
        #pragma unroll
        for (int r = 0; r < RPW; r++) {
            p[r][0] += __shfl_xor_sync(0xffffffffu, p[r][0], off);
            p[r][1] += __shfl_xor_sync(0xffffffffu, p[r][1], off);
            p[r][2] += __shfl_xor_sync(0xffffffffu, p[r][2], off);
        }
    }

    // ---- conv + LN partials per row ----
    float o[RPW][8];
    float s1[RPW], s2[RPW];
    #pragma unroll
    for (int r = 0; r < RPW; r++) {
        const float kw0 = p[r][0] + bw0;
        const float kw1 = p[r][1] + bw1;
        const float kw2 = p[r][2] + bw2;

        const float4 x0 = vv4[r][0], x1 = vv4[r][1];
        const float chL = __shfl_sync(0xffffffffu, x0.w, 31);   // ch 127
        const float chR = __shfl_sync(0xffffffffu, x1.x, 0);    // ch 128
        float l0 = __shfl_up_sync  (0xffffffffu, x0.w, 1);
        float r0 = __shfl_down_sync(0xffffffffu, x0.x, 1);
        float l1 = __shfl_up_sync  (0xffffffffu, x1.w, 1);
        float r1 = __shfl_down_sync(0xffffffffu, x1.x, 1);
        if (lane == 0)  { l0 = 0.0f; l1 = chL; }
        if (lane == 31) { r0 = chR;  r1 = 0.0f; }

        const float wA[6] = { l0, x0.x, x0.y, x0.z, x0.w, r0 };
        const float wB[6] = { l1, x1.x, x1.y, x1.z, x1.w, r1 };
        float a1 = 0.0f, a2 = 0.0f;
        #pragma unroll
        for (int i = 0; i < 4; i++) {
            const float y0 = wA[i]*kw0 + wA[i+1]*kw1 + wA[i+2]*kw2;
            const float y1 = wB[i]*kw0 + wB[i+1]*kw1 + wB[i+2]*kw2;
            o[r][i]     = y0;
            o[r][i + 4] = y1;
            a1 += y0 + y1;
            a2 += y0*y0 + y1*y1;
        }
        s1[r] = a1; s2[r] = a2;
    }

    // ---- LN butterflies: 8 independent chains ----
    #pragma unroll
    for (int off = 16; off > 0; off >>= 1) {
        #pragma unroll
        for (int r = 0; r < RPW; r++) {
            s1[r] += __shfl_xor_sync(0xffffffffu, s1[r], off);
            s2[r] += __shfl_xor_sync(0xffffffffu, s2[r], off);
        }
    }

    // ---- scale/shift + coalesced streaming stores ----
    const float4 g0  = *(const float4*)(gamma + c0);
    const float4 g1  = *(const float4*)(gamma + c1);
    const float4 bt0 = *(const float4*)(beta  + c0);
    const float4 bt1 = *(const float4*)(beta  + c1);

    #pragma unroll
    for (int r = 0; r < RPW; r++) {
        const float mu   = s1[r] * (1.0f / C_DIM);
        const float rstd = rsqrtf(s2[r] * (1.0f / C_DIM) - mu*mu + LN_EPS);
        float4 t;
        t.x = (o[r][0]-mu)*rstd*g0.x + bt0.x;
        t.y = (o[r][1]-mu)*rstd*g0.y + bt0.y;
        t.z = (o[r][2]-mu)*rstd*g0.z + bt0.z;
        t.w = (o[r][3]-mu)*rstd*g0.w + bt0.w;
        __stcs((float4*)(out + base[r] + c0), t);
        t.x = (o[r][4]-mu)*rstd*g1.x + bt1.x;
        t.y = (o[r][5]-mu)*rstd*g1.y + bt1.y;
        t.z = (o[r][6]-mu)*rstd*g1.z + bt1.z;
        t.w = (o[r][7]-mu)*rstd*g1.w + bt1.w;
        __stcs((float4*)(out + base[r] + c1), t);
    }
}

extern "C" void kernel_launch(void* const* d_in, const int* in_sizes, int n_in,
                              void* d_out, int out_size) {
    const float* q     = (const float*)d_in[0];
    const float* v     = (const float*)d_in[1];
    const float* Ww    = (const float*)d_in[2];
    const float* bw    = (const float*)d_in[3];
    const float* gamma = (const float*)d_in[4];
    const float* beta  = (const float*)d_in[5];
    float* out = (float*)d_out;

    const int rows = out_size / C_DIM;                       // 102400
    const int ctas = rows / (RPW * WARPS_PER_CTA);           // 6400
    dydw_atten_kernel<<<ctas, WARPS_PER_CTA * 32>>>(q, v, Ww, bw, gamma, beta, out);
}